// round 7
// baseline (speedup 1.0000x reference)
#include <cuda_runtime.h>
#include <cuda_fp16.h>
#include <cstdint>

// ============================================================================
// ConditionEmbedder — sm_103 (non-'a' target) mma.sync.m16n8k16 version, v2.
// R7 changes vs R6 (217.9us, occ 12%, issue 32%):
//  - <=128 regs (launch_bounds(256,2)) -> 2 CTA/SM: softmax rewritten as a
//    single pass using a tight analytic upper bound (no hv[32] array, no
//    max-reduce); exps packed fp16 unnormalized, one hmul2 normalize pass.
//  - log2e pre-scaled w1/b1 -> exp is a single ex2.approx.
//  - double-buffered B tile, ONE __syncthreads per dim (stage d+1 overlaps
//    other warps' mma(d)).
//  - ldmatrix.x4 (2 n-tiles per instruction) -> half the LDSM instructions.
// ============================================================================

static constexpr int DDIMS        = 8;
static constexpr int HDIM         = 128;
static constexpr int ROWS_PER_CTA = 128;
static constexpr int NBLOCKS      = 131072 / ROWS_PER_CTA;   // 1024
static constexpr int CTA_THREADS  = 256;                     // 8 warps

static constexpr int BROW_BYTES   = 272;                     // 256 + 16B pad
static constexpr int BTILE_BYTES  = 128 * BROW_BYTES;        // 34816

// smem layout (dynamic)
static constexpr int SMEM_LABELS  = 0;                       // 4096
static constexpr int SMEM_W1L     = 4096;                    // 4096 (w1 * log2e)
static constexpr int SMEM_B1L     = 8192;                    // 4096 (b1 * log2e)
static constexpr int SMEM_EMB     = 12288;                   // 4096
static constexpr int SMEM_STATS   = 16384;                   // hi[8],lo[8],bm[8] = 96 -> 128
static constexpr int SMEM_BT0     = 16512;
static constexpr int SMEM_BT1     = SMEM_BT0 + BTILE_BYTES;  // 51328
static constexpr int SMEM_TOTAL   = SMEM_BT1 + BTILE_BYTES;  // 86144

// Pre-converted fp16 w2, [d][k_out][h] row-major (== col-major B for the mma).
__device__ __align__(16) __half g_w2h[DDIMS * HDIM * HDIM];

__global__ void prep_w2_kernel(const float* __restrict__ w2) {
    int i = blockIdx.x * 256 + threadIdx.x;      // exactly 131072 elements
    g_w2h[i] = __float2half(w2[i]);
}

__device__ __forceinline__ uint32_t smem_to_u32(const void* p) {
    uint32_t a;
    asm("{ .reg .u64 t; cvta.to.shared.u64 t, %1; cvt.u32.u64 %0, t; }"
        : "=r"(a) : "l"(p));
    return a;
}

__device__ __forceinline__ float ex2f(float x) {
    float r;
    asm("ex2.approx.ftz.f32 %0, %1;" : "=f"(r) : "f"(x));
    return r;
}

__global__ void __launch_bounds__(CTA_THREADS, 2)
cond_embed_kernel(const float* __restrict__ labels,
                  const float* __restrict__ emb_w,
                  const float* __restrict__ w1,
                  const float* __restrict__ b1,
                  const int*   __restrict__ uncond_p,
                  float*       __restrict__ out)
{
    extern __shared__ __align__(16) char smem[];
    float* lab_sm = reinterpret_cast<float*>(smem + SMEM_LABELS);
    float* w1_sm  = reinterpret_cast<float*>(smem + SMEM_W1L);
    float* b1_sm  = reinterpret_cast<float*>(smem + SMEM_B1L);
    float* emb_sm = reinterpret_cast<float*>(smem + SMEM_EMB);
    float* st_sm  = reinterpret_cast<float*>(smem + SMEM_STATS);

    const int tid  = threadIdx.x;
    const int wid  = tid >> 5;
    const int lane = tid & 31;
    const int gr   = lane >> 2;
    const int q    = lane & 3;
    const int blk  = blockIdx.x;
    const float LOG2E = 1.44269504088896340736f;

    // ---- stage labels + log2e-scaled w1/b1 + emb ----
    for (int i = tid; i < 1024; i += CTA_THREADS) {
        lab_sm[i] = labels[(size_t)blk * 1024 + i];
        w1_sm[i]  = w1[i] * LOG2E;
        b1_sm[i]  = b1[i] * LOG2E;
        emb_sm[i] = emb_w[i];
    }
    const int force_drop = *uncond_p;
    __syncthreads();

    // ---- per-dim stats: warp wid reduces dim wid (hi/lo of w1L, max of b1L) ----
    {
        float hi = -1e30f, lo = 1e30f, bm = -1e30f;
        #pragma unroll
        for (int k = 0; k < 4; ++k) {
            float v = w1_sm[wid * HDIM + lane + 32 * k];
            hi = fmaxf(hi, v);
            lo = fminf(lo, v);
            bm = fmaxf(bm, b1_sm[wid * HDIM + lane + 32 * k]);
        }
        #pragma unroll
        for (int s = 16; s; s >>= 1) {
            hi = fmaxf(hi, __shfl_xor_sync(0xffffffffu, hi, s));
            lo = fminf(lo, __shfl_xor_sync(0xffffffffu, lo, s));
            bm = fmaxf(bm, __shfl_xor_sync(0xffffffffu, bm, s));
        }
        if (lane == 0) { st_sm[wid] = hi; st_sm[8 + wid] = lo; st_sm[16 + wid] = bm; }
    }

    // ---- stage B(0) into buffer 0 ----
    {
        const uint4* src = reinterpret_cast<const uint4*>(g_w2h);
        #pragma unroll
        for (int it = 0; it < 8; ++it) {
            int idx = tid + it * CTA_THREADS;
            *reinterpret_cast<uint4*>(smem + SMEM_BT0 + (idx >> 4) * BROW_BYTES
                                      + (idx & 15) * 16) = src[idx];
        }
    }
    __syncthreads();

    float acc[64];
    #pragma unroll
    for (int i = 0; i < 64; ++i) acc[i] = 0.0f;
    uint32_t afr[32];

    unsigned mask0 = 0, mask1 = 0;
    const int r0 = wid * 16 + gr;
    const int r1 = r0 + 8;

    const uint32_t smemB0 = smem_to_u32(smem) + SMEM_BT0;
    // ldmatrix.x4 lane base: lanes 0-7 rows nt0/k-lo, 8-15 nt0/k-hi,
    //                        16-23 nt1/k-lo, 24-31 nt1/k-hi
    const uint32_t bln4 = ((uint32_t)(lane >> 4) * 8u + (uint32_t)(lane & 7)) * BROW_BYTES
                        + (uint32_t)((lane >> 3) & 1) * 16u;

    for (int d = 0; d < DDIMS; ++d) {
        // ---- per-row softmax -> unnormalized fp16 fragments + fp32 sum ----
        const float x0 = lab_sm[r0 * DDIMS + d];
        const float x1 = lab_sm[r1 * DDIMS + d];
        const bool dr0 = ((__float_as_uint(x0) & 0x7fffffffu) > 0x7f800000u) || force_drop;
        const bool dr1 = ((__float_as_uint(x1) & 0x7fffffffu) > 0x7f800000u) || force_drop;
        if (dr0) mask0 |= 1u << d;
        if (dr1) mask1 |= 1u << d;
        const float hiL = st_sm[d], loL = st_sm[8 + d], bmL = st_sm[16 + d];

        float inva[2];
        #pragma unroll
        for (int rr = 0; rr < 2; ++rr) {
            const float xr = rr ? x1 : x0;
            const bool  dr = rr ? dr1 : dr0;
            const float xs = dr ? 0.0f : xr;
            // tight upper bound of h (log2 domain): softmax shift-invariant
            const float ub = fmaf(xs, xs >= 0.0f ? hiL : loL, bmL);
            float z = 0.0f;
            #pragma unroll
            for (int t = 0; t < 8; ++t) {
                const int cb = 16 * t + 2 * q;
                float e0 = ex2f(fmaf(xs, w1_sm[d*HDIM + cb],     b1_sm[d*HDIM + cb])     - ub);
                float e1 = ex2f(fmaf(xs, w1_sm[d*HDIM + cb + 1], b1_sm[d*HDIM + cb + 1]) - ub);
                float e2 = ex2f(fmaf(xs, w1_sm[d*HDIM + cb + 8], b1_sm[d*HDIM + cb + 8]) - ub);
                float e3 = ex2f(fmaf(xs, w1_sm[d*HDIM + cb + 9], b1_sm[d*HDIM + cb + 9]) - ub);
                z += (e0 + e1) + (e2 + e3);
                __half2 plo = __floats2half2_rn(e0, e1);
                __half2 phi = __floats2half2_rn(e2, e3);
                afr[4 * t + 0 + rr] = *reinterpret_cast<uint32_t*>(&plo);
                afr[4 * t + 2 + rr] = *reinterpret_cast<uint32_t*>(&phi);
            }
            z += __shfl_xor_sync(0xffffffffu, z, 1);
            z += __shfl_xor_sync(0xffffffffu, z, 2);
            inva[rr] = dr ? 0.0f : __fdividef(1.0f, z);
        }
        // normalize fragments (fp16 x fp16; drop rows -> exact zero)
        {
            const __half2 i0 = __half2half2(__float2half_rn(inva[0]));
            const __half2 i1 = __half2half2(__float2half_rn(inva[1]));
            #pragma unroll
            for (int t = 0; t < 8; ++t) {
                __half2* a = reinterpret_cast<__half2*>(afr + 4 * t);
                a[0] = __hmul2(a[0], i0);
                a[1] = __hmul2(a[1], i1);
                a[2] = __hmul2(a[2], i0);
                a[3] = __hmul2(a[3], i1);
            }
        }

        __syncthreads();   // all warps finished ldmatrix(d-1); stats/B(d) ready

        // ---- stage B(d+1) into other buffer (overlaps other warps' mma) ----
        if (d < DDIMS - 1) {
            const uint4* src = reinterpret_cast<const uint4*>(g_w2h + (d + 1) * HDIM * HDIM);
            char* dstb = smem + ((d + 1) & 1 ? SMEM_BT1 : SMEM_BT0);
            #pragma unroll
            for (int it = 0; it < 8; ++it) {
                int idx = tid + it * CTA_THREADS;
                *reinterpret_cast<uint4*>(dstb + (idx >> 4) * BROW_BYTES
                                          + (idx & 15) * 16) = src[idx];
            }
        }

        // ---- D += A @ B^T : 8 k-chunks x 8 nt-pairs (ldmatrix.x4 + 2 mma) ----
        const uint32_t bbuf = smemB0 + (uint32_t)(d & 1) * BTILE_BYTES + bln4;
        #pragma unroll
        for (int t = 0; t < 8; ++t) {
            #pragma unroll
            for (int p = 0; p < 8; ++p) {
                uint32_t bf0, bf1, bf2, bf3;
                asm volatile(
                    "ldmatrix.sync.aligned.m8n8.x4.shared.b16 {%0,%1,%2,%3}, [%4];"
                    : "=r"(bf0), "=r"(bf1), "=r"(bf2), "=r"(bf3)
                    : "r"(bbuf + (uint32_t)p * (16u * BROW_BYTES) + (uint32_t)t * 32u));
                asm volatile(
                    "mma.sync.aligned.m16n8k16.row.col.f32.f16.f16.f32 "
                    "{%0,%1,%2,%3}, {%4,%5,%6,%7}, {%8,%9}, {%0,%1,%2,%3};"
                    : "+f"(acc[8*p+0]), "+f"(acc[8*p+1]), "+f"(acc[8*p+2]), "+f"(acc[8*p+3])
                    : "r"(afr[4*t+0]), "r"(afr[4*t+1]), "r"(afr[4*t+2]), "r"(afr[4*t+3]),
                      "r"(bf0), "r"(bf1));
                asm volatile(
                    "mma.sync.aligned.m16n8k16.row.col.f32.f16.f16.f32 "
                    "{%0,%1,%2,%3}, {%4,%5,%6,%7}, {%8,%9}, {%0,%1,%2,%3};"
                    : "+f"(acc[8*p+4]), "+f"(acc[8*p+5]), "+f"(acc[8*p+6]), "+f"(acc[8*p+7])
                    : "r"(afr[4*t+0]), "r"(afr[4*t+1]), "r"(afr[4*t+2]), "r"(afr[4*t+3]),
                      "r"(bf2), "r"(bf3));
            }
        }
    }

    // ---- epilogue: add emb rows for dropped dims, store float2 pairs ----
    const size_t base0 = ((size_t)blk * ROWS_PER_CTA + r0) * HDIM;
    const size_t base1 = ((size_t)blk * ROWS_PER_CTA + r1) * HDIM;
    #pragma unroll
    for (int p = 0; p < 8; ++p) {
        #pragma unroll
        for (int h = 0; h < 2; ++h) {        // nt = 2p+h
            const int c = (2 * p + h) * 8 + 2 * q;
            float v0 = acc[8*p + 4*h + 0], v1 = acc[8*p + 4*h + 1];
            float v2 = acc[8*p + 4*h + 2], v3 = acc[8*p + 4*h + 3];
            unsigned m = mask0;
            while (m) {
                const int dd = __ffs(m) - 1; m &= m - 1;
                v0 += emb_sm[dd * HDIM + c];
                v1 += emb_sm[dd * HDIM + c + 1];
            }
            m = mask1;
            while (m) {
                const int dd = __ffs(m) - 1; m &= m - 1;
                v2 += emb_sm[dd * HDIM + c];
                v3 += emb_sm[dd * HDIM + c + 1];
            }
            *reinterpret_cast<float2*>(out + base0 + c) = make_float2(v0, v1);
            *reinterpret_cast<float2*>(out + base1 + c) = make_float2(v2, v3);
        }
    }
}

// ============================================================================
// kernel_launch — inputs: labels, emb_w, w1, b1, w2, train, unconditioned
//                 output: float32 [131072, 128]
// ============================================================================
extern "C" void kernel_launch(void* const* d_in, const int* in_sizes, int n_in,
                              void* d_out, int out_size)
{
    const float* labels = (const float*)d_in[0];
    const float* emb_w  = (const float*)d_in[1];
    const float* w1     = (const float*)d_in[2];
    const float* b1     = (const float*)d_in[3];
    const float* w2     = (const float*)d_in[4];
    const int*   uncond = (n_in > 6) ? (const int*)d_in[6] : (const int*)d_in[5];
    float* out = (float*)d_out;

    prep_w2_kernel<<<DDIMS * HDIM * HDIM / 256, 256>>>(w2);

    cudaFuncSetAttribute(cond_embed_kernel,
                         cudaFuncAttributeMaxDynamicSharedMemorySize, SMEM_TOTAL);
    cond_embed_kernel<<<NBLOCKS, CTA_THREADS, SMEM_TOTAL>>>(
        labels, emb_w, w1, b1, uncond, out);
}

// round 8
// speedup vs baseline: 1.4542x; 1.4542x over previous
#include <cuda_runtime.h>
#include <cuda_fp16.h>
#include <cstdint>

// ============================================================================
// ConditionEmbedder — sm_103 mma.sync.m16n8k16, v3.
// R8 vs R7 (251us, spilled at 128-reg cap): halve accumulators by splitting
// kout into two sequential halves (nh loop). acc[64]->acc[32]; natural reg
// demand ~105 -> genuine 2 CTA/SM with no spills. Softmax recomputed per half
// (MUFU has headroom); B staged as 16KB half-tiles, double buffered, one
// __syncthreads per iteration.
// ============================================================================

static constexpr int DDIMS        = 8;
static constexpr int HDIM         = 128;
static constexpr int ROWS_PER_CTA = 128;
static constexpr int NBLOCKS      = 131072 / ROWS_PER_CTA;   // 1024
static constexpr int CTA_THREADS  = 256;                     // 8 warps

static constexpr int BROW_BYTES   = 272;                     // 256 + 16B pad
static constexpr int HTILE_BYTES  = 64 * BROW_BYTES;         // 17408 (64-row half)

// smem layout (dynamic)
static constexpr int SMEM_LABELS  = 0;                       // 4096
static constexpr int SMEM_W1L     = 4096;                    // 4096 (w1 * log2e)
static constexpr int SMEM_B1L     = 8192;                    // 4096 (b1 * log2e)
static constexpr int SMEM_EMB     = 12288;                   // 4096
static constexpr int SMEM_STATS   = 16384;                   // 128
static constexpr int SMEM_BT0     = 16512;
static constexpr int SMEM_BT1     = SMEM_BT0 + HTILE_BYTES;  // 33920
static constexpr int SMEM_TOTAL   = SMEM_BT1 + HTILE_BYTES;  // 51328

// Pre-converted fp16 w2, [d][k_out][h] row-major (== col-major B for the mma).
__device__ __align__(16) __half g_w2h[DDIMS * HDIM * HDIM];

__global__ void prep_w2_kernel(const float* __restrict__ w2) {
    int i = blockIdx.x * 256 + threadIdx.x;      // exactly 131072 elements
    g_w2h[i] = __float2half(w2[i]);
}

__device__ __forceinline__ uint32_t smem_to_u32(const void* p) {
    uint32_t a;
    asm("{ .reg .u64 t; cvta.to.shared.u64 t, %1; cvt.u32.u64 %0, t; }"
        : "=r"(a) : "l"(p));
    return a;
}

__device__ __forceinline__ float ex2f(float x) {
    float r;
    asm("ex2.approx.ftz.f32 %0, %1;" : "=f"(r) : "f"(x));
    return r;
}

__global__ void __launch_bounds__(CTA_THREADS, 2)
cond_embed_kernel(const float* __restrict__ labels,
                  const float* __restrict__ emb_w,
                  const float* __restrict__ w1,
                  const float* __restrict__ b1,
                  const int*   __restrict__ uncond_p,
                  float*       __restrict__ out)
{
    extern __shared__ __align__(16) char smem[];
    float* lab_sm = reinterpret_cast<float*>(smem + SMEM_LABELS);
    float* w1_sm  = reinterpret_cast<float*>(smem + SMEM_W1L);
    float* b1_sm  = reinterpret_cast<float*>(smem + SMEM_B1L);
    float* emb_sm = reinterpret_cast<float*>(smem + SMEM_EMB);
    float* st_sm  = reinterpret_cast<float*>(smem + SMEM_STATS);

    const int tid  = threadIdx.x;
    const int wid  = tid >> 5;
    const int lane = tid & 31;
    const int gr   = lane >> 2;
    const int q    = lane & 3;
    const int blk  = blockIdx.x;
    const float LOG2E = 1.44269504088896340736f;

    // ---- stage labels + log2e-scaled w1/b1 + emb ----
    for (int i = tid; i < 1024; i += CTA_THREADS) {
        lab_sm[i] = labels[(size_t)blk * 1024 + i];
        w1_sm[i]  = w1[i] * LOG2E;
        b1_sm[i]  = b1[i] * LOG2E;
        emb_sm[i] = emb_w[i];
    }
    const int force_drop = *uncond_p;
    __syncthreads();

    // ---- per-dim stats: warp wid reduces dim wid (hi/lo of w1L, max of b1L) ----
    {
        float hi = -1e30f, lo = 1e30f, bm = -1e30f;
        #pragma unroll
        for (int k = 0; k < 4; ++k) {
            float v = w1_sm[wid * HDIM + lane + 32 * k];
            hi = fmaxf(hi, v);
            lo = fminf(lo, v);
            bm = fmaxf(bm, b1_sm[wid * HDIM + lane + 32 * k]);
        }
        #pragma unroll
        for (int s = 16; s; s >>= 1) {
            hi = fmaxf(hi, __shfl_xor_sync(0xffffffffu, hi, s));
            lo = fminf(lo, __shfl_xor_sync(0xffffffffu, lo, s));
            bm = fmaxf(bm, __shfl_xor_sync(0xffffffffu, bm, s));
        }
        if (lane == 0) { st_sm[wid] = hi; st_sm[8 + wid] = lo; st_sm[16 + wid] = bm; }
    }

    // ---- stage B(it=0): w2[0] rows 0..63 into buffer 0 ----
    {
        const uint4* src = reinterpret_cast<const uint4*>(g_w2h);
        #pragma unroll
        for (int i = 0; i < 4; ++i) {
            int idx = tid + i * CTA_THREADS;      // 0..1023
            *reinterpret_cast<uint4*>(smem + SMEM_BT0 + (idx >> 4) * BROW_BYTES
                                      + (idx & 15) * 16) = src[idx];
        }
    }
    __syncthreads();

    float acc[32];
    #pragma unroll
    for (int i = 0; i < 32; ++i) acc[i] = 0.0f;
    uint32_t afr[32];

    unsigned mask0 = 0, mask1 = 0;
    const int r0 = wid * 16 + gr;
    const int r1 = r0 + 8;

    const uint32_t smemB0 = smem_to_u32(smem) + SMEM_BT0;
    // ldmatrix.x4 lane base: lanes 0-7 rows nt0/k-lo, 8-15 nt0/k-hi,
    //                        16-23 nt1/k-lo, 24-31 nt1/k-hi
    const uint32_t bln4 = ((uint32_t)(lane >> 4) * 8u + (uint32_t)(lane & 7)) * BROW_BYTES
                        + (uint32_t)((lane >> 3) & 1) * 16u;

    // 16 iterations: it = nh*8 + d  (nh = kout half, d = condition dim)
    for (int it = 0; it < 16; ++it) {
        const int d = it & 7;

        // ---- per-row softmax -> unnormalized fp16 fragments + fp32 sum ----
        const float x0 = lab_sm[r0 * DDIMS + d];
        const float x1 = lab_sm[r1 * DDIMS + d];
        const bool dr0 = ((__float_as_uint(x0) & 0x7fffffffu) > 0x7f800000u) || force_drop;
        const bool dr1 = ((__float_as_uint(x1) & 0x7fffffffu) > 0x7f800000u) || force_drop;
        if (dr0) mask0 |= 1u << d;
        if (dr1) mask1 |= 1u << d;
        const float hiL = st_sm[d], loL = st_sm[8 + d], bmL = st_sm[16 + d];

        float inva[2];
        #pragma unroll
        for (int rr = 0; rr < 2; ++rr) {
            const float xr = rr ? x1 : x0;
            const bool  dr = rr ? dr1 : dr0;
            const float xs = dr ? 0.0f : xr;
            const float ub = fmaf(xs, xs >= 0.0f ? hiL : loL, bmL);  // tight log2-domain bound
            float z = 0.0f;
            #pragma unroll
            for (int t = 0; t < 8; ++t) {
                const int cb = 16 * t + 2 * q;
                float e0 = ex2f(fmaf(xs, w1_sm[d*HDIM + cb],     b1_sm[d*HDIM + cb])     - ub);
                float e1 = ex2f(fmaf(xs, w1_sm[d*HDIM + cb + 1], b1_sm[d*HDIM + cb + 1]) - ub);
                float e2 = ex2f(fmaf(xs, w1_sm[d*HDIM + cb + 8], b1_sm[d*HDIM + cb + 8]) - ub);
                float e3 = ex2f(fmaf(xs, w1_sm[d*HDIM + cb + 9], b1_sm[d*HDIM + cb + 9]) - ub);
                z += (e0 + e1) + (e2 + e3);
                __half2 plo = __floats2half2_rn(e0, e1);
                __half2 phi = __floats2half2_rn(e2, e3);
                afr[4 * t + 0 + rr] = *reinterpret_cast<uint32_t*>(&plo);
                afr[4 * t + 2 + rr] = *reinterpret_cast<uint32_t*>(&phi);
            }
            z += __shfl_xor_sync(0xffffffffu, z, 1);
            z += __shfl_xor_sync(0xffffffffu, z, 2);
            inva[rr] = dr ? 0.0f : __fdividef(1.0f, z);
        }
        {
            const __half2 i0 = __half2half2(__float2half_rn(inva[0]));
            const __half2 i1 = __half2half2(__float2half_rn(inva[1]));
            #pragma unroll
            for (int t = 0; t < 8; ++t) {
                __half2* a = reinterpret_cast<__half2*>(afr + 4 * t);
                a[0] = __hmul2(a[0], i0);
                a[1] = __hmul2(a[1], i1);
                a[2] = __hmul2(a[2], i0);
                a[3] = __hmul2(a[3], i1);
            }
        }

        __syncthreads();   // prev iter's ldmatrix done; this iter's B visible

        // ---- stage B(it+1) half-tile into the other buffer ----
        if (it < 15) {
            const int itn = it + 1;
            const uint4* src = reinterpret_cast<const uint4*>(
                g_w2h + (itn & 7) * HDIM * HDIM + (itn >> 3) * 64 * HDIM);
            char* dstb = smem + (itn & 1 ? SMEM_BT1 : SMEM_BT0);
            #pragma unroll
            for (int i = 0; i < 4; ++i) {
                int idx = tid + i * CTA_THREADS;
                *reinterpret_cast<uint4*>(dstb + (idx >> 4) * BROW_BYTES
                                          + (idx & 15) * 16) = src[idx];
            }
        }

        // ---- D += A @ B^T : 8 k-chunks x 4 nt-pairs (ldmatrix.x4 + 2 mma) ----
        const uint32_t bbuf = smemB0 + (uint32_t)(it & 1) * HTILE_BYTES + bln4;
        #pragma unroll
        for (int t = 0; t < 8; ++t) {
            #pragma unroll
            for (int p = 0; p < 4; ++p) {
                uint32_t bf0, bf1, bf2, bf3;
                asm volatile(
                    "ldmatrix.sync.aligned.m8n8.x4.shared.b16 {%0,%1,%2,%3}, [%4];"
                    : "=r"(bf0), "=r"(bf1), "=r"(bf2), "=r"(bf3)
                    : "r"(bbuf + (uint32_t)p * (16u * BROW_BYTES) + (uint32_t)t * 32u));
                asm volatile(
                    "mma.sync.aligned.m16n8k16.row.col.f32.f16.f16.f32 "
                    "{%0,%1,%2,%3}, {%4,%5,%6,%7}, {%8,%9}, {%0,%1,%2,%3};"
                    : "+f"(acc[8*p+0]), "+f"(acc[8*p+1]), "+f"(acc[8*p+2]), "+f"(acc[8*p+3])
                    : "r"(afr[4*t+0]), "r"(afr[4*t+1]), "r"(afr[4*t+2]), "r"(afr[4*t+3]),
                      "r"(bf0), "r"(bf1));
                asm volatile(
                    "mma.sync.aligned.m16n8k16.row.col.f32.f16.f16.f32 "
                    "{%0,%1,%2,%3}, {%4,%5,%6,%7}, {%8,%9}, {%0,%1,%2,%3};"
                    : "+f"(acc[8*p+4]), "+f"(acc[8*p+5]), "+f"(acc[8*p+6]), "+f"(acc[8*p+7])
                    : "r"(afr[4*t+0]), "r"(afr[4*t+1]), "r"(afr[4*t+2]), "r"(afr[4*t+3]),
                      "r"(bf2), "r"(bf3));
            }
        }

        // ---- end of a kout half: epilogue for columns nh*64..+64, reset acc ----
        if (d == 7) {
            const int nh = it >> 3;
            const size_t base0 = ((size_t)blk * ROWS_PER_CTA + r0) * HDIM + nh * 64;
            const size_t base1 = ((size_t)blk * ROWS_PER_CTA + r1) * HDIM + nh * 64;
            #pragma unroll
            for (int p = 0; p < 4; ++p) {
                #pragma unroll
                for (int h = 0; h < 2; ++h) {           // nt = 2p+h
                    const int c = (2 * p + h) * 8 + 2 * q;
                    float v0 = acc[8*p + 4*h + 0], v1 = acc[8*p + 4*h + 1];
                    float v2 = acc[8*p + 4*h + 2], v3 = acc[8*p + 4*h + 3];
                    const int ce = nh * 64 + c;
                    unsigned m = mask0;
                    while (m) {
                        const int dd = __ffs(m) - 1; m &= m - 1;
                        v0 += emb_sm[dd * HDIM + ce];
                        v1 += emb_sm[dd * HDIM + ce + 1];
                    }
                    m = mask1;
                    while (m) {
                        const int dd = __ffs(m) - 1; m &= m - 1;
                        v2 += emb_sm[dd * HDIM + ce];
                        v3 += emb_sm[dd * HDIM + ce + 1];
                    }
                    *reinterpret_cast<float2*>(out + base0 + c) = make_float2(v0, v1);
                    *reinterpret_cast<float2*>(out + base1 + c) = make_float2(v2, v3);
                }
            }
            #pragma unroll
            for (int i = 0; i < 32; ++i) acc[i] = 0.0f;
        }
    }
}

// ============================================================================
// kernel_launch — inputs: labels, emb_w, w1, b1, w2, train, unconditioned
//                 output: float32 [131072, 128]
// ============================================================================
extern "C" void kernel_launch(void* const* d_in, const int* in_sizes, int n_in,
                              void* d_out, int out_size)
{
    const float* labels = (const float*)d_in[0];
    const float* emb_w  = (const float*)d_in[1];
    const float* w1     = (const float*)d_in[2];
    const float* b1     = (const float*)d_in[3];
    const float* w2     = (const float*)d_in[4];
    const int*   uncond = (n_in > 6) ? (const int*)d_in[6] : (const int*)d_in[5];
    float* out = (float*)d_out;

    prep_w2_kernel<<<DDIMS * HDIM * HDIM / 256, 256>>>(w2);

    cudaFuncSetAttribute(cond_embed_kernel,
                         cudaFuncAttributeMaxDynamicSharedMemorySize, SMEM_TOTAL);
    cond_embed_kernel<<<NBLOCKS, CTA_THREADS, SMEM_TOTAL>>>(
        labels, emb_w, w1, b1, uncond, out);
}

// round 9
// speedup vs baseline: 1.5082x; 1.0371x over previous
#include <cuda_runtime.h>
#include <cuda_fp16.h>
#include <cstdint>

// ============================================================================
// ConditionEmbedder — sm_103 mma.sync.m16n8k16, v4.
// R9 vs R8 (172.5us, L1=69.5% = ceiling): softmax w1/b1 reads repacked into
// mma-fragment-ordered float4 pairs (prep kernel, log2e folded) -> 2 broadcast
// LDS.128 per k-chunk instead of 8 scattered LDS.32 (4x fewer smem wavefronts
// on the softmax path, less address ALU). Per-dim ub stats precomputed in
// prep. B staging via cp.async (no reg round-trip). Core structure unchanged.
// ============================================================================

static constexpr int DDIMS        = 8;
static constexpr int HDIM         = 128;
static constexpr int ROWS_PER_CTA = 128;
static constexpr int NBLOCKS      = 131072 / ROWS_PER_CTA;   // 1024
static constexpr int CTA_THREADS  = 256;                     // 8 warps

static constexpr int BROW_BYTES   = 272;                     // 256 + 16B pad
static constexpr int HTILE_BYTES  = 64 * BROW_BYTES;         // 17408 (64-row half)

// smem layout (dynamic)
static constexpr int SMEM_LABELS  = 0;                       // 4096
static constexpr int SMEM_EMB     = 4096;                    // 4096
static constexpr int SMEM_PK      = 8192;                    // 512 float4 = 8192
static constexpr int SMEM_STATS   = 16384;                   // 24 floats -> 128
static constexpr int SMEM_BT0     = 16512;
static constexpr int SMEM_BT1     = SMEM_BT0 + HTILE_BYTES;  // 33920
static constexpr int SMEM_TOTAL   = SMEM_BT1 + HTILE_BYTES;  // 51328

// Pre-converted fp16 w2, [d][k_out][h] row-major (== col-major B for the mma).
__device__ __align__(16) __half g_w2h[DDIMS * HDIM * HDIM];
// Fragment-ordered, log2e-scaled w1/b1: entries (d,t,q) -> cols {cb,cb+1,cb+8,cb+9},
// cb = 16t+2q. [0..255] = w, [256..511] = b.
__device__ __align__(16) float4 g_pk[512];
// Per-dim stats: [0..7] max(w1L), [8..15] min(w1L), [16..23] max(b1L)
__device__ float g_st[24];

__global__ void prep_w2_kernel(const float* __restrict__ w2) {
    int i = blockIdx.x * 256 + threadIdx.x;      // exactly 131072 elements
    g_w2h[i] = __float2half(w2[i]);
}

// 256 threads: lane l of warp d handles (t = l>>2, q = l&3).
__global__ void prep_small_kernel(const float* __restrict__ w1,
                                  const float* __restrict__ b1) {
    const int tid  = threadIdx.x;
    const int d    = tid >> 5;
    const int lane = tid & 31;
    const int t    = lane >> 2;
    const int q    = lane & 3;
    const int cb   = 16 * t + 2 * q;
    const float LOG2E = 1.44269504088896340736f;

    float w0 = w1[d * HDIM + cb]     * LOG2E;
    float w1v = w1[d * HDIM + cb + 1] * LOG2E;
    float w8 = w1[d * HDIM + cb + 8] * LOG2E;
    float w9 = w1[d * HDIM + cb + 9] * LOG2E;
    float bb0 = b1[d * HDIM + cb]     * LOG2E;
    float bb1 = b1[d * HDIM + cb + 1] * LOG2E;
    float bb8 = b1[d * HDIM + cb + 8] * LOG2E;
    float bb9 = b1[d * HDIM + cb + 9] * LOG2E;

    const int e = (d * 8 + t) * 4 + q;
    g_pk[e]       = make_float4(w0, w1v, w8, w9);
    g_pk[256 + e] = make_float4(bb0, bb1, bb8, bb9);

    // per-dim stats (each col appears exactly once across the warp's entries)
    float hi = fmaxf(fmaxf(w0, w1v), fmaxf(w8, w9));
    float lo = fminf(fminf(w0, w1v), fminf(w8, w9));
    float bm = fmaxf(fmaxf(bb0, bb1), fmaxf(bb8, bb9));
    #pragma unroll
    for (int s = 16; s; s >>= 1) {
        hi = fmaxf(hi, __shfl_xor_sync(0xffffffffu, hi, s));
        lo = fminf(lo, __shfl_xor_sync(0xffffffffu, lo, s));
        bm = fmaxf(bm, __shfl_xor_sync(0xffffffffu, bm, s));
    }
    if (lane == 0) { g_st[d] = hi; g_st[8 + d] = lo; g_st[16 + d] = bm; }
}

__device__ __forceinline__ uint32_t smem_to_u32(const void* p) {
    uint32_t a;
    asm("{ .reg .u64 t; cvta.to.shared.u64 t, %1; cvt.u32.u64 %0, t; }"
        : "=r"(a) : "l"(p));
    return a;
}

__device__ __forceinline__ float ex2f(float x) {
    float r;
    asm("ex2.approx.ftz.f32 %0, %1;" : "=f"(r) : "f"(x));
    return r;
}

__device__ __forceinline__ void cp_async16(uint32_t dst, const void* src) {
    asm volatile("cp.async.cg.shared.global [%0], [%1], 16;"
                 :: "r"(dst), "l"(src));
}

__global__ void __launch_bounds__(CTA_THREADS, 2)
cond_embed_kernel(const float* __restrict__ labels,
                  const float* __restrict__ emb_w,
                  const int*   __restrict__ uncond_p,
                  float*       __restrict__ out)
{
    extern __shared__ __align__(16) char smem[];
    float*  lab_sm = reinterpret_cast<float*>(smem + SMEM_LABELS);
    float*  emb_sm = reinterpret_cast<float*>(smem + SMEM_EMB);
    float4* pk_sm  = reinterpret_cast<float4*>(smem + SMEM_PK);
    float*  st_sm  = reinterpret_cast<float*>(smem + SMEM_STATS);

    const int tid  = threadIdx.x;
    const int wid  = tid >> 5;
    const int lane = tid & 31;
    const int gr   = lane >> 2;
    const int q    = lane & 3;
    const int blk  = blockIdx.x;

    const uint32_t smem_base = smem_to_u32(smem);

    // ---- stage labels + emb + pk + stats; B(0) via cp.async ----
    for (int i = tid; i < 1024; i += CTA_THREADS) {
        lab_sm[i] = labels[(size_t)blk * 1024 + i];
        emb_sm[i] = emb_w[i];
    }
    for (int i = tid; i < 512; i += CTA_THREADS)
        pk_sm[i] = g_pk[i];
    if (tid < 24) st_sm[tid] = g_st[tid];
    {
        const char* src = reinterpret_cast<const char*>(g_w2h);
        #pragma unroll
        for (int i = 0; i < 4; ++i) {
            int idx = tid + i * CTA_THREADS;      // 0..1023, 16B lines
            cp_async16(smem_base + SMEM_BT0 + (idx >> 4) * BROW_BYTES
                       + (idx & 15) * 16, src + idx * 16);
        }
        asm volatile("cp.async.commit_group;" ::: "memory");
    }
    const int force_drop = *uncond_p;
    asm volatile("cp.async.wait_group 0;" ::: "memory");
    __syncthreads();

    float acc[32];
    #pragma unroll
    for (int i = 0; i < 32; ++i) acc[i] = 0.0f;
    uint32_t afr[32];

    unsigned mask0 = 0, mask1 = 0;
    const int r0 = wid * 16 + gr;
    const int r1 = r0 + 8;

    const uint32_t smemB0 = smem_base + SMEM_BT0;
    // ldmatrix.x4 lane base: lanes 0-7 rows nt0/k-lo, 8-15 nt0/k-hi,
    //                        16-23 nt1/k-lo, 24-31 nt1/k-hi
    const uint32_t bln4 = ((uint32_t)(lane >> 4) * 8u + (uint32_t)(lane & 7)) * BROW_BYTES
                        + (uint32_t)((lane >> 3) & 1) * 16u;

    // 16 iterations: it = nh*8 + d  (nh = kout half, d = condition dim)
    for (int it = 0; it < 16; ++it) {
        const int d = it & 7;

        // ---- per-row softmax -> unnormalized fp16 fragments + fp32 sum ----
        const float x0 = lab_sm[r0 * DDIMS + d];
        const float x1 = lab_sm[r1 * DDIMS + d];
        const bool dr0 = ((__float_as_uint(x0) & 0x7fffffffu) > 0x7f800000u) || force_drop;
        const bool dr1 = ((__float_as_uint(x1) & 0x7fffffffu) > 0x7f800000u) || force_drop;
        if (dr0) mask0 |= 1u << d;
        if (dr1) mask1 |= 1u << d;
        const float hiL = st_sm[d], loL = st_sm[8 + d], bmL = st_sm[16 + d];
        const float4* pw = pk_sm + (d * 8) * 4 + q;        // stride 4 per t
        const float4* pb = pw + 256;

        float inva[2];
        #pragma unroll
        for (int rr = 0; rr < 2; ++rr) {
            const float xr = rr ? x1 : x0;
            const bool  dr = rr ? dr1 : dr0;
            const float xs = dr ? 0.0f : xr;
            const float ub = fmaf(xs, xs >= 0.0f ? hiL : loL, bmL);  // tight log2-domain bound
            float z = 0.0f;
            #pragma unroll
            for (int t = 0; t < 8; ++t) {
                const float4 wv = pw[t * 4];
                const float4 bv = pb[t * 4];
                float e0 = ex2f(fmaf(xs, wv.x, bv.x) - ub);
                float e1 = ex2f(fmaf(xs, wv.y, bv.y) - ub);
                float e2 = ex2f(fmaf(xs, wv.z, bv.z) - ub);
                float e3 = ex2f(fmaf(xs, wv.w, bv.w) - ub);
                z += (e0 + e1) + (e2 + e3);
                __half2 plo = __floats2half2_rn(e0, e1);
                __half2 phi = __floats2half2_rn(e2, e3);
                afr[4 * t + 0 + rr] = *reinterpret_cast<uint32_t*>(&plo);
                afr[4 * t + 2 + rr] = *reinterpret_cast<uint32_t*>(&phi);
            }
            z += __shfl_xor_sync(0xffffffffu, z, 1);
            z += __shfl_xor_sync(0xffffffffu, z, 2);
            inva[rr] = dr ? 0.0f : __fdividef(1.0f, z);
        }
        {
            const __half2 i0 = __half2half2(__float2half_rn(inva[0]));
            const __half2 i1 = __half2half2(__float2half_rn(inva[1]));
            #pragma unroll
            for (int t = 0; t < 8; ++t) {
                __half2* a = reinterpret_cast<__half2*>(afr + 4 * t);
                a[0] = __hmul2(a[0], i0);
                a[1] = __hmul2(a[1], i1);
                a[2] = __hmul2(a[2], i0);
                a[3] = __hmul2(a[3], i1);
            }
        }

        // staged B(it) visible; prev iter's ldmatrix done; prev cp.async landed
        asm volatile("cp.async.wait_group 0;" ::: "memory");
        __syncthreads();

        // ---- stage B(it+1) half-tile into the other buffer (cp.async) ----
        if (it < 15) {
            const int itn = it + 1;
            const char* src = reinterpret_cast<const char*>(
                g_w2h + (itn & 7) * HDIM * HDIM + (itn >> 3) * 64 * HDIM);
            const uint32_t dstb = smem_base + (itn & 1 ? SMEM_BT1 : SMEM_BT0);
            #pragma unroll
            for (int i = 0; i < 4; ++i) {
                int idx = tid + i * CTA_THREADS;
                cp_async16(dstb + (idx >> 4) * BROW_BYTES + (idx & 15) * 16,
                           src + idx * 16);
            }
            asm volatile("cp.async.commit_group;" ::: "memory");
        }

        // ---- D += A @ B^T : 8 k-chunks x 4 nt-pairs (ldmatrix.x4 + 2 mma) ----
        const uint32_t bbuf = smemB0 + (uint32_t)(it & 1) * HTILE_BYTES + bln4;
        #pragma unroll
        for (int t = 0; t < 8; ++t) {
            #pragma unroll
            for (int p = 0; p < 4; ++p) {
                uint32_t bf0, bf1, bf2, bf3;
                asm volatile(
                    "ldmatrix.sync.aligned.m8n8.x4.shared.b16 {%0,%1,%2,%3}, [%4];"
                    : "=r"(bf0), "=r"(bf1), "=r"(bf2), "=r"(bf3)
                    : "r"(bbuf + (uint32_t)p * (16u * BROW_BYTES) + (uint32_t)t * 32u));
                asm volatile(
                    "mma.sync.aligned.m16n8k16.row.col.f32.f16.f16.f32 "
                    "{%0,%1,%2,%3}, {%4,%5,%6,%7}, {%8,%9}, {%0,%1,%2,%3};"
                    : "+f"(acc[8*p+0]), "+f"(acc[8*p+1]), "+f"(acc[8*p+2]), "+f"(acc[8*p+3])
                    : "r"(afr[4*t+0]), "r"(afr[4*t+1]), "r"(afr[4*t+2]), "r"(afr[4*t+3]),
                      "r"(bf0), "r"(bf1));
                asm volatile(
                    "mma.sync.aligned.m16n8k16.row.col.f32.f16.f16.f32 "
                    "{%0,%1,%2,%3}, {%4,%5,%6,%7}, {%8,%9}, {%0,%1,%2,%3};"
                    : "+f"(acc[8*p+4]), "+f"(acc[8*p+5]), "+f"(acc[8*p+6]), "+f"(acc[8*p+7])
                    : "r"(afr[4*t+0]), "r"(afr[4*t+1]), "r"(afr[4*t+2]), "r"(afr[4*t+3]),
                      "r"(bf2), "r"(bf3));
            }
        }

        // ---- end of a kout half: epilogue for columns nh*64..+64, reset acc ----
        if (d == 7) {
            const int nh = it >> 3;
            const size_t base0 = ((size_t)blk * ROWS_PER_CTA + r0) * HDIM + nh * 64;
            const size_t base1 = ((size_t)blk * ROWS_PER_CTA + r1) * HDIM + nh * 64;
            #pragma unroll
            for (int p = 0; p < 4; ++p) {
                #pragma unroll
                for (int h = 0; h < 2; ++h) {           // nt = 2p+h
                    const int c = (2 * p + h) * 8 + 2 * q;
                    float v0 = acc[8*p + 4*h + 0], v1 = acc[8*p + 4*h + 1];
                    float v2 = acc[8*p + 4*h + 2], v3 = acc[8*p + 4*h + 3];
                    const int ce = nh * 64 + c;
                    unsigned m = mask0;
                    while (m) {
                        const int dd = __ffs(m) - 1; m &= m - 1;
                        v0 += emb_sm[dd * HDIM + ce];
                        v1 += emb_sm[dd * HDIM + ce + 1];
                    }
                    m = mask1;
                    while (m) {
                        const int dd = __ffs(m) - 1; m &= m - 1;
                        v2 += emb_sm[dd * HDIM + ce];
                        v3 += emb_sm[dd * HDIM + ce + 1];
                    }
                    *reinterpret_cast<float2*>(out + base0 + c) = make_float2(v0, v1);
                    *reinterpret_cast<float2*>(out + base1 + c) = make_float2(v2, v3);
                }
            }
            #pragma unroll
            for (int i = 0; i < 32; ++i) acc[i] = 0.0f;
        }
    }
}

// ============================================================================
// kernel_launch — inputs: labels, emb_w, w1, b1, w2, train, unconditioned
//                 output: float32 [131072, 128]
// ============================================================================
extern "C" void kernel_launch(void* const* d_in, const int* in_sizes, int n_in,
                              void* d_out, int out_size)
{
    const float* labels = (const float*)d_in[0];
    const float* emb_w  = (const float*)d_in[1];
    const float* w1     = (const float*)d_in[2];
    const float* b1     = (const float*)d_in[3];
    const float* w2     = (const float*)d_in[4];
    const int*   uncond = (n_in > 6) ? (const int*)d_in[6] : (const int*)d_in[5];
    float* out = (float*)d_out;

    prep_w2_kernel<<<DDIMS * HDIM * HDIM / 256, 256>>>(w2);
    prep_small_kernel<<<1, 256>>>(w1, b1);

    cudaFuncSetAttribute(cond_embed_kernel,
                         cudaFuncAttributeMaxDynamicSharedMemorySize, SMEM_TOTAL);
    cond_embed_kernel<<<NBLOCKS, CTA_THREADS, SMEM_TOTAL>>>(
        labels, emb_w, uncond, out);
}